// round 1
// baseline (speedup 1.0000x reference)
#include <cuda_runtime.h>
#include <math.h>

// Problem constants
#define B_    16
#define T_    64
#define H_    1024
#define D_    2048      // 2H
#define EMB_  512
#define MO_   1024      // maxout units
#define V_    32000
#define G3_   3072      // 3H
#define CAT_  3584      // H + EMB + D

// ---------------- scratch (device globals; no allocation allowed) ----------
__device__ float g_hemb[B_ * T_ * T_];        // h @ W_h + b_h        [b][t][j]
__device__ float g_Hih [B_ * T_ * G3_];       // h @ W_ih + b_ih      [b][t][j]
__device__ float g_s   [2][B_ * H_];          // ping-pong GRU state
__device__ float g_E   [T_ * B_ * T_];        // attention weights    [i][b][t]
__device__ float g_cat [T_ * B_ * CAT_];      // [s_new | y_emb | c] rows (i*B+b)
__device__ float g_tt  [T_ * B_ * 2 * MO_];   // t_tilde
__device__ float g_tmax[T_ * B_ * MO_];       // maxout result

// ---------------------------------------------------------------------------
__global__ void zero_state_kernel() {
    int i = blockIdx.x * blockDim.x + threadIdx.x;
    if (i < B_ * H_) g_s[0][i] = 0.0f;
}

// ---------------- generic fp32 tiled GEMM: C = A[MxK] * B[KxN] + bias -------
// BM=BN=64, BK=16, 256 threads, 4x4 per thread. All dims used are multiples
// of the tile sizes, so no bounds checks. Optional row permutation for the
// final vocab GEMM: scratch row r = i*B+b  ->  output row b*T + i.
template <bool PERMUTE>
__global__ __launch_bounds__(256)
void gemm64_kernel(const float* __restrict__ A, int lda,
                   const float* __restrict__ Bm, int ldb,
                   float* __restrict__ C, int ldc,
                   const float* __restrict__ bias, int K)
{
    __shared__ float As[16][64];   // A tile, transposed
    __shared__ float Bs[16][64];

    const int tid = threadIdx.x;
    const int tx = tid & 15;        // 0..15  -> N
    const int ty = tid >> 4;        // 0..15  -> M
    const int m0 = blockIdx.y * 64;
    const int n0 = blockIdx.x * 64;

    const int arow = tid >> 2;              // 0..63
    const int acol = (tid & 3) * 4;         // 0..12
    const int brow = tid >> 4;              // 0..15
    const int bcol = (tid & 15) * 4;        // 0..60

    float acc[4][4] = {};

    for (int k0 = 0; k0 < K; k0 += 16) {
        float4 av = *reinterpret_cast<const float4*>(
            &A[(size_t)(m0 + arow) * lda + k0 + acol]);
        float4 bv = *reinterpret_cast<const float4*>(
            &Bm[(size_t)(k0 + brow) * ldb + n0 + bcol]);
        __syncthreads();   // previous tile fully consumed
        As[acol + 0][arow] = av.x;
        As[acol + 1][arow] = av.y;
        As[acol + 2][arow] = av.z;
        As[acol + 3][arow] = av.w;
        *reinterpret_cast<float4*>(&Bs[brow][bcol]) = bv;
        __syncthreads();
#pragma unroll
        for (int k = 0; k < 16; k++) {
            float4 a4 = *reinterpret_cast<const float4*>(&As[k][ty * 4]);
            float4 b4 = *reinterpret_cast<const float4*>(&Bs[k][tx * 4]);
            float ar[4] = {a4.x, a4.y, a4.z, a4.w};
            float br[4] = {b4.x, b4.y, b4.z, b4.w};
#pragma unroll
            for (int i = 0; i < 4; i++)
#pragma unroll
                for (int j = 0; j < 4; j++)
                    acc[i][j] += ar[i] * br[j];
        }
    }

#pragma unroll
    for (int i = 0; i < 4; i++) {
        int gr = m0 + ty * 4 + i;
        int orow = PERMUTE ? ((gr & (B_ - 1)) * T_ + (gr >> 4)) : gr;
#pragma unroll
        for (int j = 0; j < 4; j++) {
            int gc = n0 + tx * 4 + j;
            C[(size_t)orow * ldc + gc] = acc[i][j] + bias[gc];
        }
    }
}

// ---------------- sequential phase: alignment + softmax --------------------
// a[b,j] = tanh( s[b,:]@W_s[:,j] + b_s[j] + hemb[b,i,j] );  e = softmax_j(a)
__global__ __launch_bounds__(256)
void attn_step_kernel(const float* __restrict__ Ws,
                      const float* __restrict__ bs, int i, int p)
{
    const int b = blockIdx.x, tid = threadIdx.x;
    __shared__ float s_sh[H_];
    const float* s_in = g_s[p] + b * H_;
#pragma unroll
    for (int q = 0; q < H_ / 256; q++) s_sh[q * 256 + tid] = s_in[q * 256 + tid];
    __syncthreads();

    const int j = tid & 63;
    const int q = tid >> 6;     // 4-way K split
    float acc = 0.0f;
    const int kbeg = q * (H_ / 4);
#pragma unroll 8
    for (int k = kbeg; k < kbeg + H_ / 4; k++)
        acc += s_sh[k] * Ws[k * T_ + j];

    __shared__ float part[4][64];
    part[q][j] = acc;
    __syncthreads();

    __shared__ float red[64];
    float a = 0.0f;
    if (tid < 64) {
        a = part[0][tid] + part[1][tid] + part[2][tid] + part[3][tid]
          + bs[tid] + g_hemb[(b * T_ + i) * T_ + tid];
        a = tanhf(a);
        red[tid] = a;
    }
    __syncthreads();
    for (int s2 = 32; s2 > 0; s2 >>= 1) {
        if (tid < s2) red[tid] = fmaxf(red[tid], red[tid + s2]);
        __syncthreads();
    }
    const float amax = red[0];
    __syncthreads();
    float ex = 0.0f;
    if (tid < 64) { ex = __expf(a - amax); red[tid] = ex; }
    __syncthreads();
    for (int s2 = 32; s2 > 0; s2 >>= 1) {
        if (tid < s2) red[tid] += red[tid + s2];
        __syncthreads();
    }
    const float ssum = red[0];
    if (tid < 64) g_E[(i * B_ + b) * T_ + tid] = ex / ssum;
}

// ---------------- sequential phase: GRU gates + state update ---------------
// gi = e @ Hih[b] (bias pre-folded), gh = s @ W_hh + b_hh, GRU pointwise.
// One thread per hidden unit k, computing all three gates.
__global__ __launch_bounds__(128)
void gru_step_kernel(const float* __restrict__ Whh,
                     const float* __restrict__ bhh, int i, int p)
{
    const int b = blockIdx.x, kc = blockIdx.y, tid = threadIdx.x;
    const int k = kc * 128 + tid;

    __shared__ float e_sh[T_];
    __shared__ float s_sh[H_];
    if (tid < 64) e_sh[tid] = g_E[(i * B_ + b) * T_ + tid];
#pragma unroll
    for (int q = 0; q < H_ / 128; q++)
        s_sh[q * 128 + tid] = g_s[p][b * H_ + q * 128 + tid];
    __syncthreads();

    float ir = 0.0f, iz = 0.0f, in_ = 0.0f;
    const float* Hb = g_Hih + (size_t)(b * T_) * G3_;
#pragma unroll 4
    for (int t = 0; t < T_; t++) {
        const float e = e_sh[t];
        const float* row = Hb + (size_t)t * G3_;
        ir  += e * row[k];
        iz  += e * row[k + H_];
        in_ += e * row[k + 2 * H_];
    }

    float hr = bhh[k], hz = bhh[k + H_], hn = bhh[k + 2 * H_];
#pragma unroll 4
    for (int kk = 0; kk < H_; kk++) {
        const float sv = s_sh[kk];
        const float* wr = Whh + (size_t)kk * G3_;
        hr += sv * wr[k];
        hz += sv * wr[k + H_];
        hn += sv * wr[k + 2 * H_];
    }

    const float r = 1.0f / (1.0f + __expf(-(ir + hr)));
    const float z = 1.0f / (1.0f + __expf(-(iz + hz)));
    const float n = tanhf(in_ + r * hn);
    const float snew = (1.0f - z) * n + z * s_sh[k];

    g_s[1 - p][b * H_ + k] = snew;
    g_cat[(size_t)(i * B_ + b) * CAT_ + k] = snew;   // concat slot 0
}

// ---------------- batched context: c[i,b,:] = e[i,b,:] @ h[b] --------------
__global__ __launch_bounds__(128)
void ctx_kernel(const float* __restrict__ h)
{
    const int b = blockIdx.x, dc = blockIdx.y, tid = threadIdx.x;
    __shared__ float sh_h[T_][128];
    __shared__ float e_sh[T_];
    const int dbase = dc * 128;
    for (int t = 0; t < T_; t++)
        sh_h[t][tid] = h[(size_t)(b * T_ + t) * D_ + dbase + tid];
    __syncthreads();

    for (int i = 0; i < T_; i++) {
        if (tid < 64) e_sh[tid] = g_E[(i * B_ + b) * T_ + tid];
        __syncthreads();
        float acc = 0.0f;
#pragma unroll 8
        for (int t = 0; t < T_; t++) acc += e_sh[t] * sh_h[t][tid];
        g_cat[(size_t)(i * B_ + b) * CAT_ + H_ + EMB_ + dbase + tid] = acc;
        __syncthreads();
    }
}

// ---------------- maxout over halves ---------------------------------------
__global__ void maxout_kernel()
{
    const int idx = blockIdx.x * blockDim.x + threadIdx.x;
    const int r = idx / MO_, m = idx - r * MO_;
    g_tmax[idx] = fmaxf(g_tt[(size_t)r * 2 * MO_ + m],
                        g_tt[(size_t)r * 2 * MO_ + MO_ + m]);
}

// ---------------------------------------------------------------------------
extern "C" void kernel_launch(void* const* d_in, const int* in_sizes, int n_in,
                              void* d_out, int out_size)
{
    (void)in_sizes; (void)n_in; (void)out_size;
    const float* h     = (const float*)d_in[0];
    const float* W_h   = (const float*)d_in[1];
    const float* b_h   = (const float*)d_in[2];
    const float* W_s   = (const float*)d_in[3];
    const float* b_s   = (const float*)d_in[4];
    const float* W_ih  = (const float*)d_in[5];
    const float* b_ih  = (const float*)d_in[6];
    const float* W_hh  = (const float*)d_in[7];
    const float* b_hh  = (const float*)d_in[8];
    const float* W_emb = (const float*)d_in[9];
    const float* b_emb = (const float*)d_in[10];
    const float* W_t   = (const float*)d_in[11];
    const float* b_t   = (const float*)d_in[12];
    const float* W_out = (const float*)d_in[13];
    const float* b_out = (const float*)d_in[14];
    float* out = (float*)d_out;

    float *p_hemb, *p_Hih, *p_cat, *p_tt, *p_tmax;
    cudaGetSymbolAddress((void**)&p_hemb, g_hemb);
    cudaGetSymbolAddress((void**)&p_Hih,  g_Hih);
    cudaGetSymbolAddress((void**)&p_cat,  g_cat);
    cudaGetSymbolAddress((void**)&p_tt,   g_tt);
    cudaGetSymbolAddress((void**)&p_tmax, g_tmax);

    zero_state_kernel<<<(B_ * H_ + 255) / 256, 256>>>();

    // Precompute (parallel): h_emb = h@W_h+b_h ; Hih = h@W_ih+b_ih
    gemm64_kernel<false><<<dim3(T_ / 64, (B_ * T_) / 64), 256>>>(
        h, D_, W_h, T_, p_hemb, T_, b_h, D_);
    gemm64_kernel<false><<<dim3(G3_ / 64, (B_ * T_) / 64), 256>>>(
        h, D_, W_ih, G3_, p_Hih, G3_, b_ih, D_);

    // Sequential recurrence (only the true data dependence)
    for (int i = 0; i < T_; i++) {
        const int p = i & 1;
        attn_step_kernel<<<B_, 256>>>(W_s, b_s, i, p);
        gru_step_kernel<<<dim3(B_, H_ / 128), 128>>>(W_hh, b_hh, i, p);
    }

    // Batched epilogue
    ctx_kernel<<<dim3(B_, D_ / 128), 128>>>(h);                       // c -> cat
    gemm64_kernel<false><<<dim3(EMB_ / 64, (T_ * B_) / 64), 256>>>(   // y_emb
        p_cat, CAT_, W_emb, EMB_, p_cat + H_, CAT_, b_emb, H_);
    gemm64_kernel<false><<<dim3(2 * MO_ / 64, (T_ * B_) / 64), 256>>>(// t_tilde
        p_cat, CAT_, W_t, 2 * MO_, p_tt, 2 * MO_, b_t, CAT_);
    maxout_kernel<<<(T_ * B_ * MO_) / 256, 256>>>();
    gemm64_kernel<true><<<dim3(V_ / 64, (T_ * B_) / 64), 256>>>(      // vocab
        p_tmax, MO_, W_out, V_, out, V_, b_out, MO_);
}

// round 2
// speedup vs baseline: 4.1276x; 4.1276x over previous
#include <cuda_runtime.h>
#include <math.h>

// Problem constants
#define B_    16
#define T_    64
#define H_    1024
#define D_    2048      // 2H
#define EMB_  512
#define MO_   1024      // maxout units
#define V_    32000
#define G3_   3072      // 3H
#define CAT_  3584      // H + EMB + D

// ---------------- scratch (device globals) ----------------------------------
__device__ float g_hemb[B_ * T_ * T_];          // h @ W_h + b_h      [b*T+t][j]
__device__ float g_Hih [B_ * T_ * G3_];         // h @ W_ih + b_ih
__device__ float g_s   [B_ * H_];               // GRU state
__device__ float g_E   [T_ * B_ * T_];          // attention weights [i][b][t]
__device__ float g_gpart[9 * B_ * G3_];         // gate partials [q][b][col]
__device__ float g_alignpart[8][B_][T_];        // s@W_s partials [kc][b][j]
__device__ float g_cat [T_ * B_ * CAT_];        // [s_new | y_emb | c]
__device__ float g_tt  [T_ * B_ * 2 * MO_];     // t_tilde
__device__ float g_tmax[T_ * B_ * MO_];         // maxout result

// ---------------------------------------------------------------------------
__global__ void init_kernel() {
    int i = blockIdx.x * blockDim.x + threadIdx.x;
    if (i < B_ * H_) g_s[i] = 0.0f;
    if (i < 8 * B_ * T_) ((float*)g_alignpart)[i] = 0.0f;
}

// ---------------- fp32 tiled GEMM (small GEMMs only) ------------------------
template <bool PERMUTE>
__global__ __launch_bounds__(256)
void gemm64_kernel(const float* __restrict__ A, int lda,
                   const float* __restrict__ Bm, int ldb,
                   float* __restrict__ C, int ldc,
                   const float* __restrict__ bias, int K)
{
    __shared__ float As[16][64];
    __shared__ float Bs[16][64];
    const int tid = threadIdx.x;
    const int tx = tid & 15, ty = tid >> 4;
    const int m0 = blockIdx.y * 64, n0 = blockIdx.x * 64;
    const int arow = tid >> 2, acol = (tid & 3) * 4;
    const int brow = tid >> 4, bcol = (tid & 15) * 4;
    float acc[4][4] = {};
    for (int k0 = 0; k0 < K; k0 += 16) {
        float4 av = *reinterpret_cast<const float4*>(&A[(size_t)(m0 + arow) * lda + k0 + acol]);
        float4 bv = *reinterpret_cast<const float4*>(&Bm[(size_t)(k0 + brow) * ldb + n0 + bcol]);
        __syncthreads();
        As[acol + 0][arow] = av.x; As[acol + 1][arow] = av.y;
        As[acol + 2][arow] = av.z; As[acol + 3][arow] = av.w;
        *reinterpret_cast<float4*>(&Bs[brow][bcol]) = bv;
        __syncthreads();
#pragma unroll
        for (int k = 0; k < 16; k++) {
            float4 a4 = *reinterpret_cast<const float4*>(&As[k][ty * 4]);
            float4 b4 = *reinterpret_cast<const float4*>(&Bs[k][tx * 4]);
            float ar[4] = {a4.x, a4.y, a4.z, a4.w};
            float br[4] = {b4.x, b4.y, b4.z, b4.w};
#pragma unroll
            for (int i = 0; i < 4; i++)
#pragma unroll
                for (int j = 0; j < 4; j++) acc[i][j] += ar[i] * br[j];
        }
    }
#pragma unroll
    for (int i = 0; i < 4; i++) {
        int gr = m0 + ty * 4 + i;
        int orow = PERMUTE ? ((gr & (B_ - 1)) * T_ + (gr >> 4)) : gr;
#pragma unroll
        for (int j = 0; j < 4; j++) {
            int gc = n0 + tx * 4 + j;
            C[(size_t)orow * ldc + gc] = acc[i][j] + bias[gc];
        }
    }
}

// ---------------- tf32 tensor-core GEMM: 128x128x16 tiles -------------------
__device__ __forceinline__ unsigned f2tf(float f) {
    unsigned r; asm("cvt.rna.tf32.f32 %0, %1;" : "=r"(r) : "f"(f)); return r;
}

template <bool PERMUTE>
__global__ __launch_bounds__(256)
void mma_gemm_kernel(const float* __restrict__ A, int lda,
                     const float* __restrict__ Bm, int ldb,
                     float* __restrict__ C, int ldc,
                     const float* __restrict__ bias, int K)
{
    __shared__ unsigned As[128][20];   // m-major, pad 20 -> conflict-free frags
    __shared__ unsigned Bs[16][136];   // k-major, pad 136 -> conflict-free frags

    const int tid = threadIdx.x;
    const int wid = tid >> 5, lane = tid & 31;
    const int wm = wid & 3, wn = wid >> 2;          // warps 4(M) x 2(N)
    const int m0 = blockIdx.y * 128, n0 = blockIdx.x * 128;

    const int arow = tid >> 2;                      // 0..63 (+64 second half)
    const int acol = (tid & 3) * 4;
    const int brow = tid >> 5;                      // 0..7 (+8)
    const int bcol = lane * 4;

    float acc[2][8][4];
#pragma unroll
    for (int mi = 0; mi < 2; mi++)
#pragma unroll
        for (int ni = 0; ni < 8; ni++)
#pragma unroll
            for (int u = 0; u < 4; u++) acc[mi][ni][u] = 0.0f;

    for (int k0 = 0; k0 < K; k0 += 16) {
        float4 a0v = *reinterpret_cast<const float4*>(&A[(size_t)(m0 + arow) * lda + k0 + acol]);
        float4 a1v = *reinterpret_cast<const float4*>(&A[(size_t)(m0 + arow + 64) * lda + k0 + acol]);
        float4 b0v = *reinterpret_cast<const float4*>(&Bm[(size_t)(k0 + brow) * ldb + n0 + bcol]);
        float4 b1v = *reinterpret_cast<const float4*>(&Bm[(size_t)(k0 + brow + 8) * ldb + n0 + bcol]);
        __syncthreads();
        As[arow][acol + 0] = f2tf(a0v.x); As[arow][acol + 1] = f2tf(a0v.y);
        As[arow][acol + 2] = f2tf(a0v.z); As[arow][acol + 3] = f2tf(a0v.w);
        As[arow + 64][acol + 0] = f2tf(a1v.x); As[arow + 64][acol + 1] = f2tf(a1v.y);
        As[arow + 64][acol + 2] = f2tf(a1v.z); As[arow + 64][acol + 3] = f2tf(a1v.w);
        Bs[brow][bcol + 0] = f2tf(b0v.x); Bs[brow][bcol + 1] = f2tf(b0v.y);
        Bs[brow][bcol + 2] = f2tf(b0v.z); Bs[brow][bcol + 3] = f2tf(b0v.w);
        Bs[brow + 8][bcol + 0] = f2tf(b1v.x); Bs[brow + 8][bcol + 1] = f2tf(b1v.y);
        Bs[brow + 8][bcol + 2] = f2tf(b1v.z); Bs[brow + 8][bcol + 3] = f2tf(b1v.w);
        __syncthreads();

#pragma unroll
        for (int k8 = 0; k8 < 2; k8++) {
            const int kb = k8 * 8;
            unsigned af[2][4], bf[8][2];
#pragma unroll
            for (int mi = 0; mi < 2; mi++) {
                int r = wm * 32 + mi * 16 + (lane >> 2);
                af[mi][0] = As[r][kb + (lane & 3)];
                af[mi][1] = As[r + 8][kb + (lane & 3)];
                af[mi][2] = As[r][kb + (lane & 3) + 4];
                af[mi][3] = As[r + 8][kb + (lane & 3) + 4];
            }
#pragma unroll
            for (int ni = 0; ni < 8; ni++) {
                int c = wn * 64 + ni * 8 + (lane >> 2);
                bf[ni][0] = Bs[kb + (lane & 3)][c];
                bf[ni][1] = Bs[kb + (lane & 3) + 4][c];
            }
#pragma unroll
            for (int mi = 0; mi < 2; mi++)
#pragma unroll
                for (int ni = 0; ni < 8; ni++) {
                    asm volatile(
                        "mma.sync.aligned.m16n8k8.row.col.f32.tf32.tf32.f32 "
                        "{%0,%1,%2,%3}, {%4,%5,%6,%7}, {%8,%9}, {%0,%1,%2,%3};"
                        : "+f"(acc[mi][ni][0]), "+f"(acc[mi][ni][1]),
                          "+f"(acc[mi][ni][2]), "+f"(acc[mi][ni][3])
                        : "r"(af[mi][0]), "r"(af[mi][1]), "r"(af[mi][2]), "r"(af[mi][3]),
                          "r"(bf[ni][0]), "r"(bf[ni][1]));
                }
        }
    }

#pragma unroll
    for (int mi = 0; mi < 2; mi++) {
        int r = m0 + wm * 32 + mi * 16 + (lane >> 2);
        int r0 = PERMUTE ? ((r & (B_ - 1)) * T_ + (r >> 4)) : r;
        int r8 = r + 8;
        int r1 = PERMUTE ? ((r8 & (B_ - 1)) * T_ + (r8 >> 4)) : r8;
#pragma unroll
        for (int ni = 0; ni < 8; ni++) {
            int c = n0 + wn * 64 + ni * 8 + (lane & 3) * 2;
            float bc0 = bias[c], bc1 = bias[c + 1];
            C[(size_t)r0 * ldc + c]     = acc[mi][ni][0] + bc0;
            C[(size_t)r0 * ldc + c + 1] = acc[mi][ni][1] + bc1;
            C[(size_t)r1 * ldc + c]     = acc[mi][ni][2] + bc0;
            C[(size_t)r1 * ldc + c + 1] = acc[mi][ni][3] + bc1;
        }
    }
}

// ---------------- sequential phase 1: gate partials (+fused attention) ------
// grid (24, 9), 256 threads. q<8: P[q][b][col] = sum_{k in q-chunk} s[b,k]*Whh[k,col]
// q==8: compute e = softmax(tanh(align + bs + hemb)) then gi = e @ Hih.
__global__ __launch_bounds__(256)
void step_gates_kernel(const float* __restrict__ Whh,
                       const float* __restrict__ bs, int i)
{
    const int cchunk = blockIdx.x;
    const int q = blockIdx.y;
    const int tid = threadIdx.x;
    const int col = tid & 127;
    const int ks  = tid >> 7;
    const int gcol = cchunk * 128 + col;

    __shared__ float sh[16][128];     // s slice (q<8) or e (q==8, cols 0..63)
    __shared__ float red[16][128];

    float acc[16];
#pragma unroll
    for (int b = 0; b < 16; b++) acc[b] = 0.0f;

    if (q < 8) {
        for (int r = tid; r < 16 * 128; r += 256) {
            int b = r >> 7, kk = r & 127;
            sh[b][kk] = g_s[b * H_ + q * 128 + kk];
        }
        __syncthreads();
        const int kbase = q * 128 + ks * 64;
        const int koff = ks * 64;
#pragma unroll 4
        for (int kk = 0; kk < 64; kk++) {
            float w = Whh[(size_t)(kbase + kk) * G3_ + gcol];
#pragma unroll
            for (int b = 0; b < 16; b++) acc[b] += w * sh[b][koff + kk];
        }
    } else {
        // fused alignment + softmax (redundant per block; identical arithmetic)
        {
            const int lane = tid & 31;
            const int b = (tid >> 5) * 2 + (lane >> 4);
            const int j0 = (lane & 15) * 4;
            float a[4];
#pragma unroll
            for (int u = 0; u < 4; u++) {
                int j = j0 + u;
                float v = bs[j] + g_hemb[(b * T_ + i) * T_ + j];
#pragma unroll
                for (int kc = 0; kc < 8; kc++) v += g_alignpart[kc][b][j];
                a[u] = tanhf(v);
            }
            float m = fmaxf(fmaxf(a[0], a[1]), fmaxf(a[2], a[3]));
#pragma unroll
            for (int o = 8; o > 0; o >>= 1) m = fmaxf(m, __shfl_xor_sync(0xffffffffu, m, o));
            float ex[4], ssum = 0.0f;
#pragma unroll
            for (int u = 0; u < 4; u++) { ex[u] = __expf(a[u] - m); ssum += ex[u]; }
#pragma unroll
            for (int o = 8; o > 0; o >>= 1) ssum += __shfl_xor_sync(0xffffffffu, ssum, o);
            float inv = 1.0f / ssum;
#pragma unroll
            for (int u = 0; u < 4; u++) {
                sh[b][j0 + u] = ex[u] * inv;
                if (cchunk == 0) g_E[(i * B_ + b) * T_ + j0 + u] = ex[u] * inv;
            }
        }
        __syncthreads();
        const int tbase = ks * 32;
#pragma unroll 2
        for (int t = 0; t < 32; t++) {
#pragma unroll
            for (int b = 0; b < 16; b++)
                acc[b] += sh[b][tbase + t] *
                          g_Hih[(size_t)(b * T_ + tbase + t) * G3_ + gcol];
        }
    }

    if (ks == 1) {
#pragma unroll
        for (int b = 0; b < 16; b++) red[b][col] = acc[b];
    }
    __syncthreads();
    if (ks == 0) {
#pragma unroll
        for (int b = 0; b < 16; b++)
            g_gpart[(q * 16 + b) * G3_ + gcol] = acc[b] + red[b][col];
    }
}

// ---------------- sequential phase 2: GRU pointwise + s@W_s partials --------
// grid (16, 8), 128 threads.
__global__ __launch_bounds__(128)
void step_update_kernel(const float* __restrict__ Ws,
                        const float* __restrict__ bhh, int i)
{
    const int b = blockIdx.x;
    const int kc = blockIdx.y;
    const int tid = threadIdx.x;
    const int k = kc * 128 + tid;

    float gr = bhh[k], gz = bhh[H_ + k], hn = bhh[2 * H_ + k];
#pragma unroll
    for (int q = 0; q < 8; q++) {
        const float* P = g_gpart + (q * 16 + b) * G3_;
        gr += P[k]; gz += P[H_ + k]; hn += P[2 * H_ + k];
    }
    const float* P8 = g_gpart + (8 * 16 + b) * G3_;
    gr += P8[k]; gz += P8[H_ + k];
    float inn = P8[2 * H_ + k];

    float r = 1.0f / (1.0f + __expf(-gr));
    float z = 1.0f / (1.0f + __expf(-gz));
    float n = tanhf(inn + r * hn);
    float sold = g_s[b * H_ + k];
    float snew = (1.0f - z) * n + z * sold;
    g_s[b * H_ + k] = snew;
    g_cat[(size_t)(i * B_ + b) * CAT_ + k] = snew;

    __shared__ float s_sh[128];
    __shared__ float redp[2][64];
    s_sh[tid] = snew;
    __syncthreads();
    const int j = tid & 63, half = tid >> 6;
    float a = 0.0f;
#pragma unroll 8
    for (int kk = half * 64; kk < half * 64 + 64; kk++)
        a += s_sh[kk] * Ws[(size_t)(kc * 128 + kk) * T_ + j];
    redp[half][j] = a;
    __syncthreads();
    if (tid < 64) g_alignpart[kc][b][tid] = redp[0][tid] + redp[1][tid];
}

// ---------------- batched context: c[i,b,:] = e[i,b,:] @ h[b] ---------------
__global__ __launch_bounds__(128)
void ctx_kernel(const float* __restrict__ h)
{
    const int b = blockIdx.x, dc = blockIdx.y, tid = threadIdx.x;
    __shared__ float sh_h[T_][128];
    __shared__ float e_sh[T_];
    const int dbase = dc * 128;
    for (int t = 0; t < T_; t++)
        sh_h[t][tid] = h[(size_t)(b * T_ + t) * D_ + dbase + tid];
    __syncthreads();
    for (int i = 0; i < T_; i++) {
        if (tid < 64) e_sh[tid] = g_E[(i * B_ + b) * T_ + tid];
        __syncthreads();
        float acc = 0.0f;
#pragma unroll 8
        for (int t = 0; t < T_; t++) acc += e_sh[t] * sh_h[t][tid];
        g_cat[(size_t)(i * B_ + b) * CAT_ + H_ + EMB_ + dbase + tid] = acc;
        __syncthreads();
    }
}

// ---------------- maxout ----------------------------------------------------
__global__ void maxout_kernel()
{
    const int idx = blockIdx.x * blockDim.x + threadIdx.x;
    const int r = idx / MO_, m = idx - r * MO_;
    g_tmax[idx] = fmaxf(g_tt[(size_t)r * 2 * MO_ + m],
                        g_tt[(size_t)r * 2 * MO_ + MO_ + m]);
}

// ---------------------------------------------------------------------------
extern "C" void kernel_launch(void* const* d_in, const int* in_sizes, int n_in,
                              void* d_out, int out_size)
{
    (void)in_sizes; (void)n_in; (void)out_size;
    const float* h     = (const float*)d_in[0];
    const float* W_h   = (const float*)d_in[1];
    const float* b_h   = (const float*)d_in[2];
    const float* W_s   = (const float*)d_in[3];
    const float* b_s   = (const float*)d_in[4];
    const float* W_ih  = (const float*)d_in[5];
    const float* b_ih  = (const float*)d_in[6];
    const float* W_hh  = (const float*)d_in[7];
    const float* b_hh  = (const float*)d_in[8];
    const float* W_emb = (const float*)d_in[9];
    const float* b_emb = (const float*)d_in[10];
    const float* W_t   = (const float*)d_in[11];
    const float* b_t   = (const float*)d_in[12];
    const float* W_out = (const float*)d_in[13];
    const float* b_out = (const float*)d_in[14];
    float* out = (float*)d_out;

    float *p_hemb, *p_Hih, *p_cat, *p_tt, *p_tmax;
    cudaGetSymbolAddress((void**)&p_hemb, g_hemb);
    cudaGetSymbolAddress((void**)&p_Hih,  g_Hih);
    cudaGetSymbolAddress((void**)&p_cat,  g_cat);
    cudaGetSymbolAddress((void**)&p_tt,   g_tt);
    cudaGetSymbolAddress((void**)&p_tmax, g_tmax);

    init_kernel<<<(B_ * H_ + 255) / 256, 256>>>();

    // Precompute: h_emb (fp32, exact since it feeds softmax), Hih (tf32 mma)
    gemm64_kernel<false><<<dim3(T_ / 64, (B_ * T_) / 64), 256>>>(
        h, D_, W_h, T_, p_hemb, T_, b_h, D_);
    mma_gemm_kernel<false><<<dim3(G3_ / 128, (B_ * T_) / 128), 256>>>(
        h, D_, W_ih, G3_, p_Hih, G3_, b_ih, D_);

    // Sequential recurrence: 2 kernels / step
    for (int i = 0; i < T_; i++) {
        step_gates_kernel<<<dim3(G3_ / 128, 9), 256>>>(W_hh, b_s, i);
        step_update_kernel<<<dim3(B_, H_ / 128), 128>>>(W_s, b_hh, i);
    }

    // Batched epilogue
    ctx_kernel<<<dim3(B_, D_ / 128), 128>>>(h);
    gemm64_kernel<false><<<dim3(EMB_ / 64, (T_ * B_) / 64), 256>>>(
        p_cat, CAT_, W_emb, EMB_, p_cat + H_, CAT_, b_emb, H_);
    mma_gemm_kernel<false><<<dim3(2 * MO_ / 128, (T_ * B_) / 128), 256>>>(
        p_cat, CAT_, W_t, 2 * MO_, p_tt, 2 * MO_, b_t, CAT_);
    maxout_kernel<<<(T_ * B_ * MO_) / 256, 256>>>();
    mma_gemm_kernel<true><<<dim3(V_ / 128, (T_ * B_) / 128), 256>>>(
        p_tmax, MO_, W_out, V_, out, V_, b_out, MO_);
}

// round 3
// speedup vs baseline: 5.0727x; 1.2290x over previous
#include <cuda_runtime.h>
#include <math.h>

// Problem constants
#define B_    16
#define T_    64
#define H_    1024
#define D_    2048      // 2H
#define EMB_  512
#define MO_   1024      // maxout units
#define V_    32000
#define G3_   3072      // 3H
#define CAT_  3584      // H + EMB + D

// ---------------- scratch (device globals) ----------------------------------
__device__ float g_hemb[B_ * T_ * T_];          // h @ W_h + b_h      [b*T+t][j]
__device__ float g_Hih [B_ * T_ * G3_];         // h @ W_ih + b_ih
__device__ float g_s   [B_ * H_];               // GRU state
__device__ float g_E   [T_ * B_ * T_];          // attention weights [i][b][t]
__device__ float g_gpart[9 * B_ * G3_];         // gate partials [q][b][col]
__device__ float g_alignpart[8][B_][T_];        // s@W_s partials [kc][b][j]
__device__ float g_cat [T_ * B_ * CAT_];        // [s_new | y_emb | c]
__device__ float g_tt  [T_ * B_ * 2 * MO_];     // t_tilde
__device__ float g_tmax[T_ * B_ * MO_];         // maxout result

// ---------------------------------------------------------------------------
__global__ void init_kernel() {
    int i = blockIdx.x * blockDim.x + threadIdx.x;
    if (i < B_ * H_) g_s[i] = 0.0f;
    if (i < 8 * B_ * T_) ((float*)g_alignpart)[i] = 0.0f;
}

// ---------------- tf32 tensor-core GEMM, 128x128x16, double-buffered --------
__device__ __forceinline__ unsigned f2tf(float f) {
    unsigned r; asm("cvt.rna.tf32.f32 %0, %1;" : "=r"(r) : "f"(f)); return r;
}

template <bool PERMUTE>
__global__ __launch_bounds__(256, 2)
void mma_gemm_kernel(const float* __restrict__ A, int lda,
                     const float* __restrict__ Bm, int ldb,
                     float* __restrict__ C, int ldc,
                     const float* __restrict__ bias, int K, int ncols)
{
    __shared__ unsigned As[2][128][20];   // m-major, pad 20
    __shared__ unsigned Bs[2][16][136];   // k-major, pad 136

    const int tid = threadIdx.x;
    const int wid = tid >> 5, lane = tid & 31;
    const int wm = wid & 3, wn = wid >> 2;          // warps 4(M) x 2(N)
    const int m0 = blockIdx.y * 128, n0 = blockIdx.x * 128;

    const int arow = tid >> 2;                      // 0..63 (+64)
    const int acol = (tid & 3) * 4;
    const int brow = tid >> 5;                      // 0..7 (+8)
    const int bcol = lane * 4;
    int colb = n0 + bcol;
    if (colb > ncols - 4) colb = ncols - 4;         // clamp (ncols mult of 4)

    float acc[2][8][4];
#pragma unroll
    for (int mi = 0; mi < 2; mi++)
#pragma unroll
        for (int ni = 0; ni < 8; ni++)
#pragma unroll
            for (int u = 0; u < 4; u++) acc[mi][ni][u] = 0.0f;

    float4 a0v, a1v, b0v, b1v;

    auto loadT = [&](int k0) {
        a0v = *reinterpret_cast<const float4*>(&A[(size_t)(m0 + arow) * lda + k0 + acol]);
        a1v = *reinterpret_cast<const float4*>(&A[(size_t)(m0 + arow + 64) * lda + k0 + acol]);
        b0v = *reinterpret_cast<const float4*>(&Bm[(size_t)(k0 + brow) * ldb + colb]);
        b1v = *reinterpret_cast<const float4*>(&Bm[(size_t)(k0 + brow + 8) * ldb + colb]);
    };
    auto stage = [&](int p) {
        As[p][arow][acol + 0] = f2tf(a0v.x); As[p][arow][acol + 1] = f2tf(a0v.y);
        As[p][arow][acol + 2] = f2tf(a0v.z); As[p][arow][acol + 3] = f2tf(a0v.w);
        As[p][arow + 64][acol + 0] = f2tf(a1v.x); As[p][arow + 64][acol + 1] = f2tf(a1v.y);
        As[p][arow + 64][acol + 2] = f2tf(a1v.z); As[p][arow + 64][acol + 3] = f2tf(a1v.w);
        Bs[p][brow][bcol + 0] = f2tf(b0v.x); Bs[p][brow][bcol + 1] = f2tf(b0v.y);
        Bs[p][brow][bcol + 2] = f2tf(b0v.z); Bs[p][brow][bcol + 3] = f2tf(b0v.w);
        Bs[p][brow + 8][bcol + 0] = f2tf(b1v.x); Bs[p][brow + 8][bcol + 1] = f2tf(b1v.y);
        Bs[p][brow + 8][bcol + 2] = f2tf(b1v.z); Bs[p][brow + 8][bcol + 3] = f2tf(b1v.w);
    };
    auto compute = [&](int p) {
#pragma unroll
        for (int k8 = 0; k8 < 2; k8++) {
            const int kb = k8 * 8;
            unsigned af[2][4], bf[8][2];
#pragma unroll
            for (int mi = 0; mi < 2; mi++) {
                int r = wm * 32 + mi * 16 + (lane >> 2);
                af[mi][0] = As[p][r][kb + (lane & 3)];
                af[mi][1] = As[p][r + 8][kb + (lane & 3)];
                af[mi][2] = As[p][r][kb + (lane & 3) + 4];
                af[mi][3] = As[p][r + 8][kb + (lane & 3) + 4];
            }
#pragma unroll
            for (int ni = 0; ni < 8; ni++) {
                int c = wn * 64 + ni * 8 + (lane >> 2);
                bf[ni][0] = Bs[p][kb + (lane & 3)][c];
                bf[ni][1] = Bs[p][kb + (lane & 3) + 4][c];
            }
#pragma unroll
            for (int mi = 0; mi < 2; mi++)
#pragma unroll
                for (int ni = 0; ni < 8; ni++) {
                    asm volatile(
                        "mma.sync.aligned.m16n8k8.row.col.f32.tf32.tf32.f32 "
                        "{%0,%1,%2,%3}, {%4,%5,%6,%7}, {%8,%9}, {%0,%1,%2,%3};"
                        : "+f"(acc[mi][ni][0]), "+f"(acc[mi][ni][1]),
                          "+f"(acc[mi][ni][2]), "+f"(acc[mi][ni][3])
                        : "r"(af[mi][0]), "r"(af[mi][1]), "r"(af[mi][2]), "r"(af[mi][3]),
                          "r"(bf[ni][0]), "r"(bf[ni][1]));
                }
        }
    };

    loadT(0); stage(0); __syncthreads();
    int buf = 0;
    for (int k0 = 16; k0 < K; k0 += 16) {
        loadT(k0);          // LDGs in flight while computing current tile
        compute(buf);
        stage(buf ^ 1);
        __syncthreads();
        buf ^= 1;
    }
    compute(buf);

#pragma unroll
    for (int mi = 0; mi < 2; mi++) {
        int r = m0 + wm * 32 + mi * 16 + (lane >> 2);
        int r0 = PERMUTE ? ((r & (B_ - 1)) * T_ + (r >> 4)) : r;
        int r8 = r + 8;
        int r1 = PERMUTE ? ((r8 & (B_ - 1)) * T_ + (r8 >> 4)) : r8;
#pragma unroll
        for (int ni = 0; ni < 8; ni++) {
            int c = n0 + wn * 64 + ni * 8 + (lane & 3) * 2;
            if (c < ncols) {
                float bc0 = bias[c], bc1 = bias[c + 1];
                C[(size_t)r0 * ldc + c]     = acc[mi][ni][0] + bc0;
                C[(size_t)r0 * ldc + c + 1] = acc[mi][ni][1] + bc1;
                C[(size_t)r1 * ldc + c]     = acc[mi][ni][2] + bc0;
                C[(size_t)r1 * ldc + c + 1] = acc[mi][ni][3] + bc1;
            }
        }
    }
}

// ---------------- sequential phase 1: gate partials (+fused attention) ------
// grid (48, 9), 256 threads. Block covers 64 output cols.
// q<8:  P[q][b][col] = sum_{k in 128-chunk} s[b,k]*Whh[k,col]  (4-way ksplit)
// q==8: e = softmax(tanh(align + bs + hemb));  gi = e @ Hih (4-way tsplit)
__global__ __launch_bounds__(256)
void step_gates_kernel(const float* __restrict__ Whh,
                       const float* __restrict__ bs, int i)
{
    const int cchunk = blockIdx.x;          // 48 chunks of 64 cols
    const int q = blockIdx.y;               // 0..8
    const int tid = threadIdx.x;
    const int col = tid & 63;
    const int ks  = tid >> 6;               // 0..3
    const int gcol = cchunk * 64 + col;

    __shared__ float s_sh[16][128];
    __shared__ float e_sh[16][64];
    __shared__ float part[4][16][64];

    float acc[16];
#pragma unroll
    for (int b = 0; b < 16; b++) acc[b] = 0.0f;

    if (q < 8) {
        for (int r = tid; r < 16 * 128; r += 256) {
            int b = r >> 7, kk = r & 127;
            s_sh[b][kk] = g_s[b * H_ + q * 128 + kk];
        }
        __syncthreads();
        const int kbase = q * 128 + ks * 32;
        const int koff = ks * 32;
#pragma unroll 16
        for (int kk = 0; kk < 32; kk++) {
            float w = Whh[(size_t)(kbase + kk) * G3_ + gcol];
#pragma unroll
            for (int b = 0; b < 16; b++) acc[b] += w * s_sh[b][koff + kk];
        }
    } else {
        // fused alignment + softmax (redundant per block; identical arithmetic)
        {
            const int lane = tid & 31;
            const int b2 = (tid >> 5) * 2 + (lane >> 4);
            const int j0 = (lane & 15) * 4;
            float a[4];
#pragma unroll
            for (int u = 0; u < 4; u++) {
                int j = j0 + u;
                float v = bs[j] + g_hemb[(b2 * T_ + i) * T_ + j];
#pragma unroll
                for (int kc = 0; kc < 8; kc++) v += g_alignpart[kc][b2][j];
                a[u] = tanhf(v);
            }
            float m = fmaxf(fmaxf(a[0], a[1]), fmaxf(a[2], a[3]));
#pragma unroll
            for (int o = 8; o > 0; o >>= 1) m = fmaxf(m, __shfl_xor_sync(0xffffffffu, m, o));
            float ex[4], ssum = 0.0f;
#pragma unroll
            for (int u = 0; u < 4; u++) { ex[u] = __expf(a[u] - m); ssum += ex[u]; }
#pragma unroll
            for (int o = 8; o > 0; o >>= 1) ssum += __shfl_xor_sync(0xffffffffu, ssum, o);
            float inv = 1.0f / ssum;
#pragma unroll
            for (int u = 0; u < 4; u++) {
                e_sh[b2][j0 + u] = ex[u] * inv;
                if (cchunk == 0) g_E[(i * B_ + b2) * T_ + j0 + u] = ex[u] * inv;
            }
        }
        __syncthreads();
        const int t0 = ks * 16;
#pragma unroll 4
        for (int t = t0; t < t0 + 16; t++) {
#pragma unroll
            for (int b = 0; b < 16; b++)
                acc[b] += e_sh[b][t] * g_Hih[(size_t)(b * T_ + t) * G3_ + gcol];
        }
    }

#pragma unroll
    for (int b = 0; b < 16; b++) part[ks][b][col] = acc[b];
    __syncthreads();
#pragma unroll
    for (int bb = 0; bb < 4; bb++) {
        int b = ks * 4 + bb;
        g_gpart[(size_t)(q * 16 + b) * G3_ + gcol] =
            part[0][b][col] + part[1][b][col] + part[2][b][col] + part[3][b][col];
    }
}

// ---------------- sequential phase 2: GRU pointwise + s@W_s partials --------
__global__ __launch_bounds__(128)
void step_update_kernel(const float* __restrict__ Ws,
                        const float* __restrict__ bhh, int i)
{
    const int b = blockIdx.x;
    const int kc = blockIdx.y;
    const int tid = threadIdx.x;
    const int k = kc * 128 + tid;

    float gr = bhh[k], gz = bhh[H_ + k], hn = bhh[2 * H_ + k];
#pragma unroll
    for (int q = 0; q < 8; q++) {
        const float* P = g_gpart + (size_t)(q * 16 + b) * G3_;
        gr += P[k]; gz += P[H_ + k]; hn += P[2 * H_ + k];
    }
    const float* P8 = g_gpart + (size_t)(8 * 16 + b) * G3_;
    gr += P8[k]; gz += P8[H_ + k];
    float inn = P8[2 * H_ + k];

    float r = 1.0f / (1.0f + __expf(-gr));
    float z = 1.0f / (1.0f + __expf(-gz));
    float n = tanhf(inn + r * hn);
    float sold = g_s[b * H_ + k];
    float snew = (1.0f - z) * n + z * sold;
    g_s[b * H_ + k] = snew;
    g_cat[(size_t)(i * B_ + b) * CAT_ + k] = snew;

    __shared__ float s_sh[128];
    __shared__ float redp[2][64];
    s_sh[tid] = snew;
    __syncthreads();
    const int j = tid & 63, half = tid >> 6;
    float a = 0.0f;
#pragma unroll 8
    for (int kk = half * 64; kk < half * 64 + 64; kk++)
        a += s_sh[kk] * Ws[(size_t)(kc * 128 + kk) * T_ + j];
    redp[half][j] = a;
    __syncthreads();
    if (tid < 64) g_alignpart[kc][b][tid] = redp[0][tid] + redp[1][tid];
}

// ---------------- batched context: c[i,b,:] = e[i,b,:] @ h[b] ---------------
__global__ __launch_bounds__(128)
void ctx_kernel(const float* __restrict__ h)
{
    const int b = blockIdx.x, dc = blockIdx.y, tid = threadIdx.x;
    __shared__ float sh_h[T_][128];
    __shared__ float e_sh[T_];
    const int dbase = dc * 128;
    for (int t = 0; t < T_; t++)
        sh_h[t][tid] = h[(size_t)(b * T_ + t) * D_ + dbase + tid];
    __syncthreads();
    for (int i = 0; i < T_; i++) {
        if (tid < 64) e_sh[tid] = g_E[(i * B_ + b) * T_ + tid];
        __syncthreads();
        float acc = 0.0f;
#pragma unroll 8
        for (int t = 0; t < T_; t++) acc += e_sh[t] * sh_h[t][tid];
        g_cat[(size_t)(i * B_ + b) * CAT_ + H_ + EMB_ + dbase + tid] = acc;
        __syncthreads();
    }
}

// ---------------- maxout ----------------------------------------------------
__global__ void maxout_kernel()
{
    const int idx = blockIdx.x * blockDim.x + threadIdx.x;
    const int r = idx / MO_, m = idx - r * MO_;
    g_tmax[idx] = fmaxf(g_tt[(size_t)r * 2 * MO_ + m],
                        g_tt[(size_t)r * 2 * MO_ + MO_ + m]);
}

// ---------------------------------------------------------------------------
extern "C" void kernel_launch(void* const* d_in, const int* in_sizes, int n_in,
                              void* d_out, int out_size)
{
    (void)in_sizes; (void)n_in; (void)out_size;
    const float* h     = (const float*)d_in[0];
    const float* W_h   = (const float*)d_in[1];
    const float* b_h   = (const float*)d_in[2];
    const float* W_s   = (const float*)d_in[3];
    const float* b_s   = (const float*)d_in[4];
    const float* W_ih  = (const float*)d_in[5];
    const float* b_ih  = (const float*)d_in[6];
    const float* W_hh  = (const float*)d_in[7];
    const float* b_hh  = (const float*)d_in[8];
    const float* W_emb = (const float*)d_in[9];
    const float* b_emb = (const float*)d_in[10];
    const float* W_t   = (const float*)d_in[11];
    const float* b_t   = (const float*)d_in[12];
    const float* W_out = (const float*)d_in[13];
    const float* b_out = (const float*)d_in[14];
    float* out = (float*)d_out;

    float *p_hemb, *p_Hih, *p_cat, *p_tt, *p_tmax;
    cudaGetSymbolAddress((void**)&p_hemb, g_hemb);
    cudaGetSymbolAddress((void**)&p_Hih,  g_Hih);
    cudaGetSymbolAddress((void**)&p_cat,  g_cat);
    cudaGetSymbolAddress((void**)&p_tt,   g_tt);
    cudaGetSymbolAddress((void**)&p_tmax, g_tmax);

    init_kernel<<<(B_ * H_ + 255) / 256, 256>>>();

    // Precompute: h_emb = h@W_h+b_h (N=64, guarded) ; Hih = h@W_ih+b_ih
    mma_gemm_kernel<false><<<dim3(1, (B_ * T_) / 128), 256>>>(
        h, D_, W_h, T_, p_hemb, T_, b_h, D_, T_);
    mma_gemm_kernel<false><<<dim3(G3_ / 128, (B_ * T_) / 128), 256>>>(
        h, D_, W_ih, G3_, p_Hih, G3_, b_ih, D_, G3_);

    // Sequential recurrence: 2 kernels / step
    for (int i = 0; i < T_; i++) {
        step_gates_kernel<<<dim3(G3_ / 64, 9), 256>>>(W_hh, b_s, i);
        step_update_kernel<<<dim3(B_, H_ / 128), 128>>>(W_s, b_hh, i);
    }

    // Batched epilogue
    ctx_kernel<<<dim3(B_, D_ / 128), 128>>>(h);
    mma_gemm_kernel<false><<<dim3(EMB_ / 128, (T_ * B_) / 128), 256>>>(
        p_cat, CAT_, W_emb, EMB_, p_cat + H_, CAT_, b_emb, H_, EMB_);
    mma_gemm_kernel<false><<<dim3(2 * MO_ / 128, (T_ * B_) / 128), 256>>>(
        p_cat, CAT_, W_t, 2 * MO_, p_tt, 2 * MO_, b_t, CAT_, 2 * MO_);
    maxout_kernel<<<(T_ * B_ * MO_) / 256, 256>>>();
    mma_gemm_kernel<true><<<dim3(V_ / 128, (T_ * B_) / 128), 256>>>(
        p_tmax, MO_, W_out, V_, out, V_, b_out, MO_, V_);
}